// round 8
// baseline (speedup 1.0000x reference)
#include <cuda_runtime.h>

// GetCostVolume: out[b, c2, d, h, w], B=4 C=32 D=48 H=64 W=128
//   c2 <  32 : x[b, c2, h, w]        if w >= d else 0
//   c2 >= 32 : y[b, c2-32, h, w-d]   if w >= d else 0
//
// R7 = R6 traffic shape + concurrency: d-loop split across blockIdx.z (4
// chunks of 12). Grid 4096 blocks -> restores occupancy so enough store
// wavefronts are in flight to saturate HBM write bandwidth.
//   - x float4 in a register, masked per d (x-half).
//   - y row in smem with 48-float zero prefix: shifted read needs no mask.
//   - padded smem p(i)=i+(i>>5): stride-4 lane reads conflict-free.

#define D_   48
#define DCH  12          // d per block (48 / 4)
#define SY_STRIDE 184    // > p(175)=180

__global__ __launch_bounds__(256) void cost_volume_kernel(
    const float* __restrict__ x,
    const float* __restrict__ y,
    float* __restrict__ out)
{
    __shared__ float s_y[8][SY_STRIDE];

    int t  = threadIdx.x;
    int w4 = t & 31;
    int hs = t >> 5;                  // 0..7 (warp id = h sub-row)
    int ht = blockIdx.x;              // 0..7, h tile
    int bc = blockIdx.y;              // b*32 + c
    int d0 = blockIdx.z * DCH;        // 0, 12, 24, 36
    int h  = (ht << 3) + hs;

    int rowv = (bc * 64 + h) * 32;    // float4 offset of (b,c,h) row

    // Zero prefix slots [0,48) for all 8 rows
    for (int idx = t; idx < 8 * 48; idx += 256) {
        int r = idx / 48, i = idx - r * 48;
        s_y[r][i + (i >> 5)] = 0.0f;
    }

    // Stage y row into padded slots 48+
    {
        float4 v = reinterpret_cast<const float4*>(y)[rowv + w4];
        int i = 48 + (w4 << 2);
        s_y[hs][(i + 0) + ((i + 0) >> 5)] = v.x;
        s_y[hs][(i + 1) + ((i + 1) >> 5)] = v.y;
        s_y[hs][(i + 2) + ((i + 2) >> 5)] = v.z;
        s_y[hs][(i + 3) + ((i + 3) >> 5)] = v.w;
    }

    float4 xv = reinterpret_cast<const float4*>(x)[rowv + w4];

    __syncthreads();

    int w0 = w4 << 2;
    int b  = bc >> 5;
    int c  = bc & 31;
    int hw = (h << 5) + w4;
    int basex = ((b * 64 + c) * D_) * 2048 + hw;  // float4 units, c2 = c
    int basey = basex + 32 * D_ * 2048;           // c2 = c + 32

    float4* outv = reinterpret_cast<float4*>(out);
    const float* yr = s_y[hs];

#pragma unroll
    for (int k = 0; k < DCH; k++) {
        int d = d0 + k;

        float4 vx;
        vx.x = (w0 + 0 >= d) ? xv.x : 0.0f;
        vx.y = (w0 + 1 >= d) ? xv.y : 0.0f;
        vx.z = (w0 + 2 >= d) ? xv.z : 0.0f;
        vx.w = (w0 + 3 >= d) ? xv.w : 0.0f;

        int i0 = 48 + w0 - d;                     // always >= 1
        float4 vy;
        vy.x = yr[(i0 + 0) + ((i0 + 0) >> 5)];
        vy.y = yr[(i0 + 1) + ((i0 + 1) >> 5)];
        vy.z = yr[(i0 + 2) + ((i0 + 2) >> 5)];
        vy.w = yr[(i0 + 3) + ((i0 + 3) >> 5)];

        int doff = d << 11;
        outv[basex + doff] = vx;
        outv[basey + doff] = vy;
    }
}

extern "C" void kernel_launch(void* const* d_in, const int* in_sizes, int n_in,
                              void* d_out, int out_size)
{
    const float* x = (const float*)d_in[0];
    const float* y = (const float*)d_in[1];
    float* out = (float*)d_out;

    dim3 grid(8, 128, 4);   // (h tile, b*32+c, d chunk) = 4096 blocks
    cost_volume_kernel<<<grid, 256>>>(x, y, out);
}